// round 6
// baseline (speedup 1.0000x reference)
#include <cuda_runtime.h>
#include <math.h>

#define NN 100000
#define NE 3200000
#define HID 16
#define NBLK 391                 // ceil(NN/256)
#define NP (NBLK * 256)          // 100096 padded

// Scratch (static device globals — zero-initialized at load)
__device__ int   d_cnt[NP];      // per-dst edge counts; re-zeroed in s3 each call
__device__ int   d_bsum[NBLK];
__device__ int   d_bpre[NBLK];
__device__ int   d_off[NN + 1];  // CSR offsets (by dst)
__device__ int   d_cur[NN];      // fill cursors; re-zeroed in k_wdeg each call
__device__ int2  d_adj[NE];      // (src, weight-bits) sorted by dst
__device__ float d_dinv[NN];
__device__ float d_g  [NN * HID];
__device__ float d_agg[NN * HID];

// ---- 1. count edges per destination -------------------------------------
__global__ void k_count(const int* __restrict__ col) {
    int e = blockIdx.x * blockDim.x + threadIdx.x;
    if (e < NE) atomicAdd(&d_cnt[col[e]], 1);
}

// ---- 2a. per-block sums --------------------------------------------------
__global__ void k_scan1() {
    __shared__ int s[256];
    int t = threadIdx.x;
    s[t] = d_cnt[blockIdx.x * 256 + t];
    __syncthreads();
    for (int d = 128; d > 0; d >>= 1) {
        if (t < d) s[t] += s[t + d];
        __syncthreads();
    }
    if (t == 0) d_bsum[blockIdx.x] = s[0];
}

// ---- 2b. scan of block sums (single block) -------------------------------
__global__ void k_scan2() {
    __shared__ int s[512];
    int t = threadIdx.x;
    int v = (t < NBLK) ? d_bsum[t] : 0;
    s[t] = v;
    __syncthreads();
    for (int d = 1; d < 512; d <<= 1) {
        int a = (t >= d) ? s[t - d] : 0;
        __syncthreads();
        s[t] += a;
        __syncthreads();
    }
    if (t < NBLK) d_bpre[t] = s[t] - v;   // exclusive
}

// ---- 2c. final offsets; reset counts for next replay ----------------------
__global__ void k_scan3() {
    __shared__ int s[256];
    int t  = threadIdx.x;
    int gi = blockIdx.x * 256 + t;
    int v  = d_cnt[gi];
    s[t] = v;
    __syncthreads();
    for (int d = 1; d < 256; d <<= 1) {
        int a = (t >= d) ? s[t - d] : 0;
        __syncthreads();
        s[t] += a;
        __syncthreads();
    }
    if (gi <= NN) d_off[gi] = d_bpre[blockIdx.x] + s[t] - v;  // exclusive
    d_cnt[gi] = 0;
}

// ---- 3. fill CSR: scatter (src, w) into dst-sorted slots ------------------
__global__ void k_fill(const int* __restrict__ row,
                       const int* __restrict__ col,
                       const float* __restrict__ ew) {
    int e = blockIdx.x * blockDim.x + threadIdx.x;
    if (e >= NE) return;
    int dst = col[e];
    int p = d_off[dst] + atomicAdd(&d_cur[dst], 1);
    d_adj[p] = make_int2(row[e], __float_as_int(ew[e]));
}

// ---- 4. weighted degree -> dinv (warp per node); reset cursors ------------
__global__ void k_wdeg() {
    int gw   = (blockIdx.x * blockDim.x + threadIdx.x) >> 5;
    int lane = threadIdx.x & 31;
    if (gw >= NN) return;
    int beg = d_off[gw], end = d_off[gw + 1];
    float sum = 0.0f;
    for (int i = beg + lane; i < end; i += 32)
        sum += __int_as_float(d_adj[i].y);
#pragma unroll
    for (int m = 16; m > 0; m >>= 1)
        sum += __shfl_xor_sync(0xffffffffu, sum, m);
    if (lane == 0) {
        float v = 1.0f + sum;              // +1 self-loop
        d_dinv[gw] = rsqrtf(v);
        d_cur[gw]  = 0;                    // reset fill cursor for next replay
    }
}

// ---- 5. layer-1 GEMM: g = dinv * (x @ W1) ---------------------------------
#define WPAD 144
__global__ void k_gemm1(const float* __restrict__ x,
                        const float* __restrict__ W1) {
    __shared__ float xs[16 * 128];
    __shared__ float Wt[HID * WPAD];
    int t = threadIdx.x;
    int base = blockIdx.x * 16;
    int nvalid = NN - base; if (nvalid > 16) nvalid = 16;

    const float4* xg = (const float4*)x + (size_t)base * 32;
    float4* xs4 = (float4*)xs;
    int n4 = nvalid * 32;
    for (int j = t; j < n4; j += 256) xs4[j] = xg[j];
    for (int j = t; j < 128 * HID; j += 256) {
        int k = j >> 4, c = j & 15;
        Wt[c * WPAD + k] = W1[j];
    }
    __syncthreads();

    int nloc = t >> 4;
    int node = base + nloc;
    int c    = t & 15;
    if (node >= NN) return;

    float acc = 0.0f;
    const float4* xrow = (const float4*)(xs + nloc * 128);
    const float*  wrow = Wt + c * WPAD;
#pragma unroll
    for (int kk = 0; kk < 32; kk++) {
        float4 xv = xrow[kk];
        float4 wv = *(const float4*)(wrow + kk * 4);
        acc += xv.x * wv.x + xv.y * wv.y + xv.z * wv.z + xv.w * wv.w;
    }
    d_g[node * HID + c] = d_dinv[node] * acc;
}

// ---- 6. aggregation (warp per node, no atomics) ---------------------------
// Lane l handles edge-slot l>>2, channel-quad l&3: 8 edges in flight/warp.
__global__ void k_agg() {
    int gw   = (blockIdx.x * blockDim.x + threadIdx.x) >> 5;
    int lane = threadIdx.x & 31;
    if (gw >= NN) return;
    int beg = d_off[gw], end = d_off[gw + 1];
    int es = lane >> 2, q = lane & 3;

    float4 acc = make_float4(0.f, 0.f, 0.f, 0.f);
    for (int i = beg + es; i < end; i += 8) {
        int2 a   = d_adj[i];                 // broadcast within quad
        float w  = __int_as_float(a.y);
        float4 g = __ldg((const float4*)d_g + a.x * 4 + q);
        acc.x += w * g.x; acc.y += w * g.y;
        acc.z += w * g.z; acc.w += w * g.w;
    }
#pragma unroll
    for (int m = 4; m < 32; m <<= 1) {
        acc.x += __shfl_xor_sync(0xffffffffu, acc.x, m);
        acc.y += __shfl_xor_sync(0xffffffffu, acc.y, m);
        acc.z += __shfl_xor_sync(0xffffffffu, acc.z, m);
        acc.w += __shfl_xor_sync(0xffffffffu, acc.w, m);
    }
    if (lane < 4) ((float4*)d_agg)[gw * 4 + lane] = acc;
}

// ---- 7. fused: h = relu(dinv*(agg+g)+b1);  g = dinv*(h @ W2) ---------------
__global__ void k_combine_gemm2(const float* __restrict__ b1,
                                const float* __restrict__ W2) {
    __shared__ float hs[16 * HID];
    __shared__ float W2s[HID * HID];
    int t = threadIdx.x;
    if (t < HID * HID) W2s[t] = W2[t];

    int nloc = t >> 4;
    int node = blockIdx.x * 16 + nloc;
    int c    = t & 15;
    bool ok  = (node < NN);
    float dv = 0.0f;
    int idx  = 0;
    if (ok) {
        idx = node * HID + c;
        dv  = d_dinv[node];
        float v = dv * (d_agg[idx] + d_g[idx]) + b1[c];
        hs[t] = fmaxf(v, 0.0f);
    }
    __syncthreads();
    if (!ok) return;

    float acc = 0.0f;
#pragma unroll
    for (int k = 0; k < HID; k++)
        acc += hs[nloc * HID + k] * W2s[k * HID + c];

    d_g[idx] = dv * acc;
}

// ---- 8. final: out = relu(dinv*(agg+g)+b2) @ Wout + bout -------------------
__global__ void k_out(const float* __restrict__ b2,
                      const float* __restrict__ Wout,
                      const float* __restrict__ bout,
                      float* __restrict__ out) {
    int i = blockIdx.x * blockDim.x + threadIdx.x;
    if (i >= NN) return;
    float dv = d_dinv[i];
    const float4* a4 = (const float4*)d_agg + i * 4;
    const float4* g4 = (const float4*)d_g   + i * 4;
    float s = 0.0f;
#pragma unroll
    for (int q = 0; q < 4; q++) {
        float4 a = a4[q], g = g4[q];
        int c = q * 4;
        s += fmaxf(dv * (a.x + g.x) + __ldg(b2 + c + 0), 0.0f) * __ldg(Wout + c + 0);
        s += fmaxf(dv * (a.y + g.y) + __ldg(b2 + c + 1), 0.0f) * __ldg(Wout + c + 1);
        s += fmaxf(dv * (a.z + g.z) + __ldg(b2 + c + 2), 0.0f) * __ldg(Wout + c + 2);
        s += fmaxf(dv * (a.w + g.w) + __ldg(b2 + c + 3), 0.0f) * __ldg(Wout + c + 3);
    }
    out[i] = s + __ldg(bout);
}

extern "C" void kernel_launch(void* const* d_in, const int* in_sizes, int n_in,
                              void* d_out, int out_size) {
    const float* x    = (const float*)d_in[0];
    const int*   ei   = (const int*)d_in[1];   // [2, NE] int32
    const float* ea   = (const float*)d_in[2];
    const float* W1   = (const float*)d_in[5];
    const float* b1   = (const float*)d_in[6];
    const float* W2   = (const float*)d_in[7];
    const float* b2   = (const float*)d_in[8];
    const float* Wout = (const float*)d_in[9];
    const float* bout = (const float*)d_in[10];
    float*       out  = (float*)d_out;

    const int* row = ei;
    const int* col = ei + NE;

    const int T = 256;
    int gE  = (NE + T - 1) / T;            // edge-wise
    int gG  = (NN + 15) / 16;              // 16 nodes/block
    int gW  = (NN * 32 + T - 1) / T;       // warp-per-node
    int gN  = (NN + T - 1) / T;            // node-wise

    // CSR build (d_cnt / d_cur are zero on entry; reset inside the pipeline)
    k_count<<<gE, T>>>(col);
    k_scan1<<<NBLK, 256>>>();
    k_scan2<<<1, 512>>>();
    k_scan3<<<NBLK, 256>>>();              // also zeroes d_cnt
    k_fill<<<gE, T>>>(row, col, ea);
    k_wdeg<<<gW, T>>>();                   // also zeroes d_cur

    // layer 1
    k_gemm1<<<gG, T>>>(x, W1);
    k_agg<<<gW, T>>>();
    k_combine_gemm2<<<gG, T>>>(b1, W2);

    // layer 2
    k_agg<<<gW, T>>>();

    // fused combine + output projection
    k_out<<<gN, T>>>(b2, Wout, bout, out);
}